// round 1
// baseline (speedup 1.0000x reference)
#include <cuda_runtime.h>
#include <math.h>

// Problem constants
#define NB   32
#define NL   4096
#define NFT  512
#define NH   512
#define NC   1025
#define MTOT (NB * NL)   // 131072

// Scratch (device globals; no allocation allowed)
__device__ float g_base[NB * NH];        // b1[h] + sum_c summary[b,c]*W1[h,512+c]
__device__ float g_logits[4 * MTOT];     // partial logits, one slab per h-tile

// ---------------------------------------------------------------------------
// Accurate-enough tanh, independent of -use_fast_math:
// tanh(x) = 1 - 2/(exp2(2*log2(e)*x) + 1).  ex2/rcp approx err ~1e-6 abs.
// Handles +-inf saturation correctly (e->inf => 1, e->0 => -1).
// ---------------------------------------------------------------------------
__device__ __forceinline__ float fast_tanh(float x) {
    float t = x * 2.885390081777927f;  // 2 * log2(e)
    float e;
    asm("ex2.approx.f32 %0, %1;" : "=f"(e) : "f"(t));
    float r;
    asm("rcp.approx.f32 %0, %1;" : "=f"(r) : "f"(e + 1.0f));
    return 1.0f - 2.0f * r;
}

__device__ __forceinline__ float fast_exp(float x) {
    float t = x * 1.4426950408889634f;  // log2(e)
    float e;
    asm("ex2.approx.f32 %0, %1;" : "=f"(e) : "f"(t));
    return e;
}

// ---------------------------------------------------------------------------
// K0: per-batch base[b,h] = b1[h] + sum_{c<512} summary[b,c] * W1[h, 512+c]
// ---------------------------------------------------------------------------
__global__ void base_kernel(const float* __restrict__ summary,
                            const float* __restrict__ W1,
                            const float* __restrict__ b1) {
    int b = blockIdx.x;
    int h = threadIdx.x;  // 512 threads
    __shared__ float ss[512];
    ss[h] = summary[b * 512 + h];
    __syncthreads();
    const float* w = W1 + (size_t)h * NC + 512;
    float acc = b1[h];
#pragma unroll 8
    for (int c = 0; c < 512; c++) acc += ss[c] * w[c];
    g_base[b * NH + h] = acc;
}

// ---------------------------------------------------------------------------
// K1: fused GEMM + epilogue.
//   For m-tile (128) x h-tile (128): acc[m,h] = sum_{k<512} ts[m,k]*W1[h,k]
//   pre = acc + base[b,h] + coverage[m]*W1[h,1024]
//   partial_logit[m] = sum_h tanh(pre) * W2[h]   -> g_logits[hTile][m]
// ---------------------------------------------------------------------------
#define TM 128
#define TN 128
#define TK 32
#define SSTR 132   // padded row stride (floats); keeps float4 alignment

__global__ __launch_bounds__(256, 2) void gemm_logits_kernel(
    const float* __restrict__ ts, const float* __restrict__ W1,
    const float* __restrict__ W2, const float* __restrict__ coverage) {
    __shared__ float sA[TK * SSTR];  // [k][m]
    __shared__ float sB[TK * SSTR];  // [k][h]

    const int m0 = blockIdx.x * TM;
    const int h0 = blockIdx.y * TN;
    const int tid = threadIdx.x;
    const int tx = tid & 15;   // h-dim position
    const int ty = tid >> 4;   // m-dim position

    float acc[8][8];
#pragma unroll
    for (int i = 0; i < 8; i++)
#pragma unroll
        for (int j = 0; j < 8; j++) acc[i][j] = 0.0f;

    for (int k0 = 0; k0 < 512; k0 += TK) {
        // Load A tile: 128 rows x 32 k, float4 along k (ts rows are 2KB-aligned)
#pragma unroll
        for (int i = 0; i < 4; i++) {
            int e = tid + i * 256;          // [0,1024) float4 slots
            int r = e >> 3;                 // m row in tile
            int kq = e & 7;                 // float4 index along k
            float4 v = *(const float4*)(ts + (size_t)(m0 + r) * 512 + k0 + kq * 4);
            sA[(kq * 4 + 0) * SSTR + r] = v.x;
            sA[(kq * 4 + 1) * SSTR + r] = v.y;
            sA[(kq * 4 + 2) * SSTR + r] = v.z;
            sA[(kq * 4 + 3) * SSTR + r] = v.w;
        }
        // Load B tile: W1 rows have odd stride 1025 (only 4B aligned) -> scalar loads
#pragma unroll
        for (int i = 0; i < 16; i++) {
            int e = tid + i * 256;          // [0,4096)
            int r = e >> 5;                 // h row in tile
            int k = e & 31;
            sB[k * SSTR + r] = W1[(size_t)(h0 + r) * NC + k0 + k];
        }
        __syncthreads();

#pragma unroll 8
        for (int kk = 0; kk < TK; kk++) {
            float4 a0 = *(const float4*)&sA[kk * SSTR + ty * 4];
            float4 a1 = *(const float4*)&sA[kk * SSTR + 64 + ty * 4];
            float4 b0 = *(const float4*)&sB[kk * SSTR + tx * 4];
            float4 b1v = *(const float4*)&sB[kk * SSTR + 64 + tx * 4];
            float av[8] = {a0.x, a0.y, a0.z, a0.w, a1.x, a1.y, a1.z, a1.w};
            float bv[8] = {b0.x, b0.y, b0.z, b0.w, b1v.x, b1v.y, b1v.z, b1v.w};
#pragma unroll
            for (int i = 0; i < 8; i++)
#pragma unroll
                for (int j = 0; j < 8; j++) acc[i][j] += av[i] * bv[j];
        }
        __syncthreads();
    }

    // ---- epilogue ----
    const int b = m0 >> 12;  // m0 / 4096; a 128-tile never crosses a batch
    float w2v[8], basev[8], wcov[8];
#pragma unroll
    for (int j = 0; j < 8; j++) {
        int hl = (j < 4) ? (tx * 4 + j) : (64 + tx * 4 + j - 4);
        int h = h0 + hl;
        w2v[j] = W2[h];
        basev[j] = g_base[b * NH + h];
        wcov[j] = W1[(size_t)h * NC + 1024];
    }

    float rowsum[8];
    int mloc[8];
#pragma unroll
    for (int i = 0; i < 8; i++) {
        int ml = (i < 4) ? (ty * 4 + i) : (64 + ty * 4 + i - 4);
        mloc[i] = ml;
        float cov = coverage[m0 + ml];  // coverage flattened [B,1,L] == m index
        float s = 0.0f;
#pragma unroll
        for (int j = 0; j < 8; j++) {
            float pre = acc[i][j] + basev[j] + cov * wcov[j];
            s += fast_tanh(pre) * w2v[j];
        }
        rowsum[i] = s;
    }

    __syncthreads();
    float* red = sA;  // reuse: 128 x 16 floats
#pragma unroll
    for (int i = 0; i < 8; i++) red[mloc[i] * 16 + tx] = rowsum[i];
    __syncthreads();

    if (tid < 128) {
        float s = 0.0f;
#pragma unroll
        for (int t = 0; t < 16; t++) s += red[tid * 16 + t];
        g_logits[(size_t)blockIdx.y * MTOT + m0 + tid] = s;
    }
}

// ---------------------------------------------------------------------------
// K2: per-batch masked softmax. Sums the 4 h-tile partials, writes attention.
// ---------------------------------------------------------------------------
__global__ __launch_bounds__(256) void softmax_kernel(const int* __restrict__ tlen,
                                                      float* __restrict__ att_out) {
    int b = blockIdx.x;
    int tid = threadIdx.x;
    __shared__ float sl[NL];
    __shared__ float rbuf[256];
    int len = tlen[b];

    for (int l = tid; l < NL; l += 256) {
        int m = b * NL + l;
        sl[l] = g_logits[m] + g_logits[MTOT + m] + g_logits[2 * MTOT + m] +
                g_logits[3 * MTOT + m];
    }
    __syncthreads();

    float mx = -INFINITY;
    for (int l = tid; l < len; l += 256) mx = fmaxf(mx, sl[l]);
    rbuf[tid] = mx;
    __syncthreads();
    for (int s = 128; s > 0; s >>= 1) {
        if (tid < s) rbuf[tid] = fmaxf(rbuf[tid], rbuf[tid + s]);
        __syncthreads();
    }
    mx = rbuf[0];
    __syncthreads();

    float sum = 0.0f;
    for (int l = tid; l < len; l += 256) {
        float e = fast_exp(sl[l] - mx);
        sl[l] = e;
        sum += e;
    }
    rbuf[tid] = sum;
    __syncthreads();
    for (int s = 128; s > 0; s >>= 1) {
        if (tid < s) rbuf[tid] = rbuf[tid] + rbuf[tid + s];
        __syncthreads();
    }
    float inv = 1.0f / rbuf[0];

    for (int l = tid; l < NL; l += 256)
        att_out[b * NL + l] = (l < len) ? sl[l] * inv : 0.0f;
}

// ---------------------------------------------------------------------------
// K3: context[b,f] = sum_l att[b,l] * ts[b,l,f].  Grid (B, 4 f-chunks of 128).
// ---------------------------------------------------------------------------
__global__ __launch_bounds__(128) void context_kernel(
    const float* __restrict__ ts, const float* __restrict__ att,
    float* __restrict__ ctx) {
    int b = blockIdx.x;
    int f = blockIdx.y * 128 + threadIdx.x;
    __shared__ float sa[512];

    const float* tsb = ts + (size_t)b * NL * 512 + f;
    const float* ab = att + b * NL;

    float acc0 = 0.f, acc1 = 0.f, acc2 = 0.f, acc3 = 0.f;
    for (int l0 = 0; l0 < NL; l0 += 512) {
        for (int j = threadIdx.x; j < 512; j += 128) sa[j] = ab[l0 + j];
        __syncthreads();
#pragma unroll 4
        for (int j = 0; j < 512; j += 4) {
            acc0 += sa[j + 0] * tsb[(size_t)(l0 + j + 0) * 512];
            acc1 += sa[j + 1] * tsb[(size_t)(l0 + j + 1) * 512];
            acc2 += sa[j + 2] * tsb[(size_t)(l0 + j + 2) * 512];
            acc3 += sa[j + 3] * tsb[(size_t)(l0 + j + 3) * 512];
        }
        __syncthreads();
    }
    ctx[b * 512 + f] = (acc0 + acc1) + (acc2 + acc3);
}

// ---------------------------------------------------------------------------
// Launch. Inputs (metadata order):
//   0 text_states [32,4096,512] f32, 1 summary [32,512] f32, 2 coverage [32,1,4096] f32,
//   3 W1 [512,1025] f32, 4 b1 [512] f32, 5 W2 [1,512] f32, 6 b2 [1] f32 (cancels in
//   softmax -> unused), 7 text_length [32] i32.
// Output: context_vector [32,512] followed by attention [32,1,4096] (147456 f32).
// ---------------------------------------------------------------------------
extern "C" void kernel_launch(void* const* d_in, const int* in_sizes, int n_in,
                              void* d_out, int out_size) {
    const float* ts  = (const float*)d_in[0];
    const float* ss  = (const float*)d_in[1];
    const float* cov = (const float*)d_in[2];
    const float* W1  = (const float*)d_in[3];
    const float* b1  = (const float*)d_in[4];
    const float* W2  = (const float*)d_in[5];
    const int*   tl  = (const int*)d_in[7];
    float* out = (float*)d_out;
    float* ctx_out = out;                    // [32,512]
    float* att_out = out + NB * NFT;         // [32,4096]

    base_kernel<<<NB, 512>>>(ss, W1, b1);
    gemm_logits_kernel<<<dim3(MTOT / TM, NH / TN), 256>>>(ts, W1, W2, cov);
    softmax_kernel<<<NB, 256>>>(tl, att_out);
    context_kernel<<<dim3(NB, 4), 128>>>(ts, att_out, ctx_out);
}

// round 3
// speedup vs baseline: 2.5041x; 2.5041x over previous
#include <cuda_runtime.h>
#include <cuda_bf16.h>
#include <math.h>
#include <stdint.h>

// ---------------------------------------------------------------------------
// Problem constants
// ---------------------------------------------------------------------------
#define NB   32
#define NL   4096
#define NH   512
#define NC   1025
#define MTOT (NB * NL)   // 131072

// GEMM tiling
#define MT   128         // m rows per CTA
#define HT   128         // h cols per CTA
#define KC   64          // k per stage
#define NSTAGES 8        // 512 / 64

// SMEM layout (bytes), per buffer: Ah, Al, Bh, Bl each 128 rows x 72 bf16 (144B)
#define ROWB    144
#define TILEB   18432                 // 128 * 144
#define OFF_AL  TILEB
#define OFF_BH  (2 * TILEB)
#define OFF_BL  (3 * TILEB)
#define BUFB    (4 * TILEB)           // 73728
#define SMEM_TOTAL (2 * BUFB)         // 147456

// ---------------------------------------------------------------------------
// Device scratch
// ---------------------------------------------------------------------------
__device__ float g_base[NB * NH];
__device__ float g_logits[4 * MTOT];         // 4 h-tile partial logits
__device__ __nv_bfloat16 g_Bh[NH * 512];
__device__ __nv_bfloat16 g_Bl[NH * 512];
__device__ float g_ctx_part[32 * NB * 512];

// ---------------------------------------------------------------------------
// helpers
// ---------------------------------------------------------------------------
__device__ __forceinline__ uint32_t smem_u32(const void* p) {
    uint32_t a;
    asm("{ .reg .u64 t; cvta.to.shared.u64 t, %1; cvt.u32.u64 %0, t; }"
        : "=r"(a) : "l"(p));
    return a;
}

__device__ __forceinline__ void ldsm4(uint32_t addr, uint32_t& r0, uint32_t& r1,
                                      uint32_t& r2, uint32_t& r3) {
    asm volatile("ldmatrix.sync.aligned.m8n8.x4.shared.b16 {%0,%1,%2,%3}, [%4];"
                 : "=r"(r0), "=r"(r1), "=r"(r2), "=r"(r3) : "r"(addr));
}

__device__ __forceinline__ void mma16816(float* d, uint32_t a0, uint32_t a1,
                                         uint32_t a2, uint32_t a3, uint32_t b0,
                                         uint32_t b1) {
    asm volatile(
        "mma.sync.aligned.m16n8k16.row.col.f32.bf16.bf16.f32 "
        "{%0,%1,%2,%3}, {%4,%5,%6,%7}, {%8,%9}, {%0,%1,%2,%3};"
        : "+f"(d[0]), "+f"(d[1]), "+f"(d[2]), "+f"(d[3])
        : "r"(a0), "r"(a1), "r"(a2), "r"(a3), "r"(b0), "r"(b1));
}

__device__ __forceinline__ void cpasync16(uint32_t dst, const void* src) {
    asm volatile("cp.async.cg.shared.global [%0], [%1], 16;"
                 :: "r"(dst), "l"(src) : "memory");
}
#define CP_COMMIT() asm volatile("cp.async.commit_group;" ::: "memory")
#define CP_WAIT0()  asm volatile("cp.async.wait_group 0;" ::: "memory")

__device__ __forceinline__ float fast_tanh(float x) {
    float t = x * 2.885390081777927f;  // 2*log2(e)
    float e;
    asm("ex2.approx.f32 %0, %1;" : "=f"(e) : "f"(t));
    float r;
    asm("rcp.approx.f32 %0, %1;" : "=f"(r) : "f"(e + 1.0f));
    return 1.0f - 2.0f * r;
}
__device__ __forceinline__ float fast_exp(float x) {
    float t = x * 1.4426950408889634f;
    float e;
    asm("ex2.approx.f32 %0, %1;" : "=f"(e) : "f"(t));
    return e;
}
__device__ __forceinline__ uint32_t pack_bf2(__nv_bfloat16 a, __nv_bfloat16 b) {
    __nv_bfloat162 v = __halves2bfloat162(a, b);
    return *reinterpret_cast<uint32_t*>(&v);
}

// ---------------------------------------------------------------------------
// K-1: W1[:,0:512] -> bf16 hi/lo
// ---------------------------------------------------------------------------
__global__ void convB_kernel(const float* __restrict__ W1) {
    int h = blockIdx.x;
    int k = threadIdx.x;
    float x = W1[(size_t)h * NC + k];
    __nv_bfloat16 hi = __float2bfloat16(x);
    g_Bh[h * 512 + k] = hi;
    g_Bl[h * 512 + k] = __float2bfloat16(x - __bfloat162float(hi));
}

// ---------------------------------------------------------------------------
// K0: base[b,h] = b1[h] + sum_c summary[b,c]*W1[h,512+c]
// ---------------------------------------------------------------------------
__global__ void base_kernel(const float* __restrict__ summary,
                            const float* __restrict__ W1,
                            const float* __restrict__ b1) {
    int b = blockIdx.x;
    int h = threadIdx.x;
    __shared__ float ss[512];
    ss[h] = summary[b * 512 + h];
    __syncthreads();
    const float* w = W1 + (size_t)h * NC + 512;
    float acc = b1[h];
#pragma unroll 8
    for (int c = 0; c < 512; c++) acc += ss[c] * w[c];
    g_base[b * NH + h] = acc;
}

// ---------------------------------------------------------------------------
// K1: HMMA GEMM (3-pass bf16 hi/lo) + fused tanh/W2 epilogue.
// Grid (1024, 4), 256 threads = 8 warps (4 m-quads x 2 n-halves).
// ---------------------------------------------------------------------------
__global__ __launch_bounds__(256, 1) void gemm_kernel(
    const float* __restrict__ ts, const float* __restrict__ W1,
    const float* __restrict__ W2, const float* __restrict__ coverage) {
    extern __shared__ char smem[];
    const uint32_t sb = smem_u32(smem);
    const int tid = threadIdx.x;
    const int lane = tid & 31;
    const int warp = tid >> 5;
    const int wm = warp & 3;   // m quadrant (32 rows)
    const int wn = warp >> 2;  // n half (64 cols)
    const int m0 = blockIdx.x * MT;
    const int h0 = blockIdx.y * HT;

    // ldmatrix base addresses (within a buffer's Ah / Bh region)
    const uint32_t aBase =
        sb + (uint32_t)((wm * 32 + (lane & 15)) * ROWB + (lane >> 4) * 16);
    const uint32_t bBase =
        sb + OFF_BH +
        (uint32_t)((wn * 64 + (lane & 7) + ((lane >> 4) & 1) * 8) * ROWB +
                   ((lane >> 3) & 1) * 16);

    float acc[2][8][4];
#pragma unroll
    for (int i = 0; i < 2; i++)
#pragma unroll
        for (int j = 0; j < 8; j++)
#pragma unroll
            for (int c = 0; c < 4; c++) acc[i][j][c] = 0.0f;

    // ---------------- prologue: stage 0 ----------------
    {
#pragma unroll
        for (int i = 0; i < 4; i++) {
            int e = tid + i * 256;
            int r = e >> 3, c = e & 7;
            uint32_t dst = sb + OFF_BH + (uint32_t)(r * ROWB + c * 16);
            cpasync16(dst, g_Bh + (size_t)(h0 + r) * 512 + c * 8);
            cpasync16(dst + TILEB, g_Bl + (size_t)(h0 + r) * 512 + c * 8);
        }
        CP_COMMIT();
#pragma unroll
        for (int i = 0; i < 8; i++) {
            int e = tid + i * 256;
            int r = e >> 4, q = e & 15;
            float4 v = *(const float4*)(ts + (size_t)(m0 + r) * 512 + q * 4);
            __nv_bfloat16 hx = __float2bfloat16(v.x);
            __nv_bfloat16 hy = __float2bfloat16(v.y);
            __nv_bfloat16 hz = __float2bfloat16(v.z);
            __nv_bfloat16 hw = __float2bfloat16(v.w);
            uint32_t off = (uint32_t)(r * ROWB + q * 8);
            *(uint2*)(smem + off) = make_uint2(pack_bf2(hx, hy), pack_bf2(hz, hw));
            *(uint2*)(smem + OFF_AL + off) = make_uint2(
                pack_bf2(__float2bfloat16(v.x - __bfloat162float(hx)),
                         __float2bfloat16(v.y - __bfloat162float(hy))),
                pack_bf2(__float2bfloat16(v.z - __bfloat162float(hz)),
                         __float2bfloat16(v.w - __bfloat162float(hw))));
        }
        CP_WAIT0();
        __syncthreads();
    }

    // ---------------- main loop ----------------
    for (int s = 0; s < NSTAGES; s++) {
        const uint32_t bo = (uint32_t)((s & 1) * BUFB);
        const uint32_t nbo = bo ^ BUFB;

        float4 av[8];
        if (s < NSTAGES - 1) {
            const int k0n = (s + 1) * KC;
#pragma unroll
            for (int i = 0; i < 4; i++) {
                int e = tid + i * 256;
                int r = e >> 3, c = e & 7;
                uint32_t dst = sb + nbo + OFF_BH + (uint32_t)(r * ROWB + c * 16);
                cpasync16(dst, g_Bh + (size_t)(h0 + r) * 512 + k0n + c * 8);
                cpasync16(dst + TILEB, g_Bl + (size_t)(h0 + r) * 512 + k0n + c * 8);
            }
            CP_COMMIT();
#pragma unroll
            for (int i = 0; i < 8; i++) {
                int e = tid + i * 256;
                int r = e >> 4, q = e & 15;
                av[i] = *(const float4*)(ts + (size_t)(m0 + r) * 512 + k0n + q * 4);
            }
        }

        // compute: 3 passes (AhBh, AhBl, AlBh)
#pragma unroll
        for (int p = 0; p < 3; p++) {
            const uint32_t aOff = bo + ((p == 2) ? (uint32_t)OFF_AL - 0u : 0u) -
                                  ((p == 2) ? 0u : 0u) + ((p == 2) ? 0u : 0u);
            const uint32_t aO = bo + ((p == 2) ? (uint32_t)TILEB : 0u);
            const uint32_t bO = bo + ((p == 1) ? (uint32_t)TILEB : 0u);
            (void)aOff;
#pragma unroll
            for (int ks = 0; ks < 4; ks++) {
                uint32_t a00, a01, a02, a03, a10, a11, a12, a13;
                ldsm4(aBase + aO + ks * 32, a00, a01, a02, a03);
                ldsm4(aBase + aO + ks * 32 + 16 * ROWB, a10, a11, a12, a13);
#pragma unroll
                for (int tp = 0; tp < 4; tp++) {
                    uint32_t b0, b1, b2, b3;
                    ldsm4(bBase + bO + ks * 32 + tp * 16 * ROWB, b0, b1, b2, b3);
                    mma16816(acc[0][2 * tp], a00, a01, a02, a03, b0, b1);
                    mma16816(acc[0][2 * tp + 1], a00, a01, a02, a03, b2, b3);
                    mma16816(acc[1][2 * tp], a10, a11, a12, a13, b0, b1);
                    mma16816(acc[1][2 * tp + 1], a10, a11, a12, a13, b2, b3);
                }
            }
        }

        if (s < NSTAGES - 1) {
#pragma unroll
            for (int i = 0; i < 8; i++) {
                int e = tid + i * 256;
                int r = e >> 4, q = e & 15;
                float4 v = av[i];
                __nv_bfloat16 hx = __float2bfloat16(v.x);
                __nv_bfloat16 hy = __float2bfloat16(v.y);
                __nv_bfloat16 hz = __float2bfloat16(v.z);
                __nv_bfloat16 hw = __float2bfloat16(v.w);
                uint32_t off = nbo + (uint32_t)(r * ROWB + q * 8);
                *(uint2*)(smem + off) =
                    make_uint2(pack_bf2(hx, hy), pack_bf2(hz, hw));
                *(uint2*)(smem + TILEB + off) = make_uint2(
                    pack_bf2(__float2bfloat16(v.x - __bfloat162float(hx)),
                             __float2bfloat16(v.y - __bfloat162float(hy))),
                    pack_bf2(__float2bfloat16(v.z - __bfloat162float(hz)),
                             __float2bfloat16(v.w - __bfloat162float(hw))));
            }
            CP_WAIT0();
        }
        __syncthreads();
    }

    // ---------------- epilogue ----------------
    const int b = m0 >> 12;
    float* s_w2 = (float*)(smem);            // 128 floats
    float* s_base = (float*)(smem + 512);    // 128
    float* s_wcov = (float*)(smem + 1024);   // 128
    float* red = (float*)(smem + 1536);      // 128 x 2
    if (tid < 128) {
        int h = h0 + tid;
        s_w2[tid] = W2[h];
        s_base[tid] = g_base[b * NH + tid + (h0)];
        s_wcov[tid] = W1[(size_t)h * NC + 1024];
    }
    __syncthreads();

#pragma unroll
    for (int tm = 0; tm < 2; tm++) {
#pragma unroll
        for (int rh = 0; rh < 2; rh++) {
            int m_local = wm * 32 + tm * 16 + rh * 8 + (lane >> 2);
            float cov = coverage[m0 + m_local];
            float rs = 0.0f;
#pragma unroll
            for (int tn = 0; tn < 8; tn++) {
                int h = wn * 64 + tn * 8 + (lane & 3) * 2;
                float p0 = acc[tm][tn][rh * 2 + 0] + s_base[h] + cov * s_wcov[h];
                float p1 =
                    acc[tm][tn][rh * 2 + 1] + s_base[h + 1] + cov * s_wcov[h + 1];
                rs += fast_tanh(p0) * s_w2[h] + fast_tanh(p1) * s_w2[h + 1];
            }
            rs += __shfl_xor_sync(0xffffffffu, rs, 1);
            rs += __shfl_xor_sync(0xffffffffu, rs, 2);
            if ((lane & 3) == 0) red[m_local * 2 + wn] = rs;
        }
    }
    __syncthreads();
    if (tid < 128)
        g_logits[(size_t)blockIdx.y * MTOT + m0 + tid] =
            red[tid * 2] + red[tid * 2 + 1];
}

// ---------------------------------------------------------------------------
// K3: per-batch masked softmax over 4 summed partial-logit slabs
// ---------------------------------------------------------------------------
__global__ __launch_bounds__(256) void softmax_kernel(const int* __restrict__ tlen,
                                                      float* __restrict__ att_out) {
    int b = blockIdx.x;
    int tid = threadIdx.x;
    __shared__ float sl[NL];
    __shared__ float rbuf[256];
    int len = tlen[b];

    for (int l = tid; l < NL; l += 256) {
        int m = b * NL + l;
        sl[l] = (g_logits[m] + g_logits[MTOT + m]) +
                (g_logits[2 * MTOT + m] + g_logits[3 * MTOT + m]);
    }
    __syncthreads();

    float mx = -INFINITY;
    for (int l = tid; l < len; l += 256) mx = fmaxf(mx, sl[l]);
    rbuf[tid] = mx;
    __syncthreads();
    for (int s = 128; s > 0; s >>= 1) {
        if (tid < s) rbuf[tid] = fmaxf(rbuf[tid], rbuf[tid + s]);
        __syncthreads();
    }
    mx = rbuf[0];
    __syncthreads();

    float sum = 0.0f;
    for (int l = tid; l < len; l += 256) {
        float e = fast_exp(sl[l] - mx);
        sl[l] = e;
        sum += e;
    }
    rbuf[tid] = sum;
    __syncthreads();
    for (int s = 128; s > 0; s >>= 1) {
        if (tid < s) rbuf[tid] = rbuf[tid] + rbuf[tid + s];
        __syncthreads();
    }
    float inv = 1.0f / rbuf[0];

    for (int l = tid; l < NL; l += 256)
        att_out[b * NL + l] = (l < len) ? sl[l] * inv : 0.0f;
}

// ---------------------------------------------------------------------------
// K4/K5: context partials + reduce
// ---------------------------------------------------------------------------
__global__ __launch_bounds__(256) void ctx_part_kernel(
    const float* __restrict__ ts, const float* __restrict__ att,
    const int* __restrict__ tlen) {
    int b = blockIdx.x;
    int c = blockIdx.y;
    int tid = threadIdx.x;
    float* out = g_ctx_part + ((size_t)c * NB + b) * 512;

    if (c * 128 >= tlen[b]) {
        out[tid] = 0.0f;
        out[tid + 256] = 0.0f;
        return;
    }

    __shared__ float sa[128];
    if (tid < 128) sa[tid] = att[b * NL + c * 128 + tid];
    __syncthreads();

    const float* base = ts + ((size_t)b * NL + c * 128) * 512;
    float a0 = 0.f, a1 = 0.f;
#pragma unroll 4
    for (int l = 0; l < 128; l++) {
        float wv = sa[l];
        a0 += wv * base[(size_t)l * 512 + tid];
        a1 += wv * base[(size_t)l * 512 + 256 + tid];
    }
    out[tid] = a0;
    out[tid + 256] = a1;
}

__global__ __launch_bounds__(512) void ctx_reduce_kernel(float* __restrict__ ctx) {
    int b = blockIdx.x;
    int f = threadIdx.x;
    float s = 0.0f;
#pragma unroll
    for (int c = 0; c < 32; c++) s += g_ctx_part[((size_t)c * NB + b) * 512 + f];
    ctx[b * 512 + f] = s;
}

// ---------------------------------------------------------------------------
// Launch
// ---------------------------------------------------------------------------
extern "C" void kernel_launch(void* const* d_in, const int* in_sizes, int n_in,
                              void* d_out, int out_size) {
    const float* ts  = (const float*)d_in[0];
    const float* ss  = (const float*)d_in[1];
    const float* cov = (const float*)d_in[2];
    const float* W1  = (const float*)d_in[3];
    const float* b1  = (const float*)d_in[4];
    const float* W2  = (const float*)d_in[5];
    const int*   tl  = (const int*)d_in[7];
    float* out = (float*)d_out;
    float* ctx_out = out;             // [32,512]
    float* att_out = out + NB * 512;  // [32,4096]

    cudaFuncSetAttribute(gemm_kernel,
                         cudaFuncAttributeMaxDynamicSharedMemorySize, SMEM_TOTAL);

    convB_kernel<<<NH, 512>>>(W1);
    base_kernel<<<NB, 512>>>(ss, W1, b1);
    gemm_kernel<<<dim3(MTOT / MT, 4), 256, SMEM_TOTAL>>>(ts, W1, W2, cov);
    softmax_kernel<<<NB, 256>>>(tl, att_out);
    ctx_part_kernel<<<dim3(NB, 32), 256>>>(ts, att_out, tl);
    ctx_reduce_kernel<<<NB, 512>>>(ctx_out);
}

// round 4
// speedup vs baseline: 4.0594x; 1.6211x over previous
#include <cuda_runtime.h>
#include <cuda_bf16.h>
#include <math.h>
#include <stdint.h>

// ---------------------------------------------------------------------------
// Problem constants
// ---------------------------------------------------------------------------
#define NB   32
#define NL   4096
#define NH   512
#define NC   1025
#define MTOT (NB * NL)   // 131072

// GEMM tiling
#define MT   128         // m rows per CTA
#define KC   64          // k per stage
#define NSTAGES 8        // 512 / 64

// SMEM layout: per buffer, Ah/Al/Bh/Bl tiles of 128 rows x 64 bf16 (128B) + 16B pad
#define ROWB    144
#define TILEB   (128 * ROWB)          // 18432
#define BUFB    (4 * TILEB)           // 73728
#define SM_TAB  (2 * BUFB)            // 147456: w2|base|wcov|red|logit_acc
#define SMEM_TOTAL (SM_TAB + 3072)    // 150528

// ---------------------------------------------------------------------------
// Device scratch (static; no runtime allocation)
// ---------------------------------------------------------------------------
__device__ float g_base[NB * NH];
__device__ float g_logits[MTOT];
__device__ __nv_bfloat16 g_Bh[NH * 512];
__device__ __nv_bfloat16 g_Bl[NH * 512];
__device__ __nv_bfloat16 g_Ah[(size_t)MTOT * 512];   // 128 MB
__device__ __nv_bfloat16 g_Al[(size_t)MTOT * 512];   // 128 MB
__device__ float g_ctx_part[32 * NB * 512];

// ---------------------------------------------------------------------------
// helpers
// ---------------------------------------------------------------------------
__device__ __forceinline__ uint32_t smem_u32(const void* p) {
    uint32_t a;
    asm("{ .reg .u64 t; cvta.to.shared.u64 t, %1; cvt.u32.u64 %0, t; }"
        : "=r"(a) : "l"(p));
    return a;
}

__device__ __forceinline__ void ldsm4(uint32_t addr, uint32_t& r0, uint32_t& r1,
                                      uint32_t& r2, uint32_t& r3) {
    asm volatile("ldmatrix.sync.aligned.m8n8.x4.shared.b16 {%0,%1,%2,%3}, [%4];"
                 : "=r"(r0), "=r"(r1), "=r"(r2), "=r"(r3) : "r"(addr));
}

__device__ __forceinline__ void mma16816(float* d, uint32_t a0, uint32_t a1,
                                         uint32_t a2, uint32_t a3, uint32_t b0,
                                         uint32_t b1) {
    asm volatile(
        "mma.sync.aligned.m16n8k16.row.col.f32.bf16.bf16.f32 "
        "{%0,%1,%2,%3}, {%4,%5,%6,%7}, {%8,%9}, {%0,%1,%2,%3};"
        : "+f"(d[0]), "+f"(d[1]), "+f"(d[2]), "+f"(d[3])
        : "r"(a0), "r"(a1), "r"(a2), "r"(a3), "r"(b0), "r"(b1));
}

__device__ __forceinline__ void cpasync16(uint32_t dst, const void* src) {
    asm volatile("cp.async.cg.shared.global [%0], [%1], 16;"
                 :: "r"(dst), "l"(src) : "memory");
}
#define CP_COMMIT() asm volatile("cp.async.commit_group;" ::: "memory")
#define CP_WAIT0()  asm volatile("cp.async.wait_group 0;" ::: "memory")

__device__ __forceinline__ float fast_tanh(float x) {
    float t = x * 2.885390081777927f;  // 2*log2(e)
    float e;
    asm("ex2.approx.f32 %0, %1;" : "=f"(e) : "f"(t));
    float r;
    asm("rcp.approx.f32 %0, %1;" : "=f"(r) : "f"(e + 1.0f));
    return 1.0f - 2.0f * r;
}
__device__ __forceinline__ float fast_exp(float x) {
    float t = x * 1.4426950408889634f;
    float e;
    asm("ex2.approx.f32 %0, %1;" : "=f"(e) : "f"(t));
    return e;
}
__device__ __forceinline__ uint32_t pack_bf2(__nv_bfloat16 a, __nv_bfloat16 b) {
    __nv_bfloat162 v = __halves2bfloat162(a, b);
    return *reinterpret_cast<uint32_t*>(&v);
}

// ---------------------------------------------------------------------------
// K-1a: ts -> bf16 hi/lo, active tiles only
// ---------------------------------------------------------------------------
__global__ __launch_bounds__(256) void convA_kernel(const float* __restrict__ ts,
                                                    const int* __restrict__ tlen) {
    int bid = blockIdx.x;
    int b = bid >> 5;
    int l0 = (bid & 31) * 128;
    if (l0 >= tlen[b]) return;
    size_t m0 = (size_t)bid * 128;
#pragma unroll 4
    for (int i = 0; i < 64; i++) {
        int e = threadIdx.x + i * 256;  // 0..16383 float4 slots
        int r = e >> 7, q = e & 127;
        size_t idx = (m0 + r) * 512 + q * 4;
        float4 v = *(const float4*)(ts + idx);
        __nv_bfloat16 hx = __float2bfloat16(v.x);
        __nv_bfloat16 hy = __float2bfloat16(v.y);
        __nv_bfloat16 hz = __float2bfloat16(v.z);
        __nv_bfloat16 hw = __float2bfloat16(v.w);
        *(uint2*)(g_Ah + idx) = make_uint2(pack_bf2(hx, hy), pack_bf2(hz, hw));
        *(uint2*)(g_Al + idx) = make_uint2(
            pack_bf2(__float2bfloat16(v.x - __bfloat162float(hx)),
                     __float2bfloat16(v.y - __bfloat162float(hy))),
            pack_bf2(__float2bfloat16(v.z - __bfloat162float(hz)),
                     __float2bfloat16(v.w - __bfloat162float(hw))));
    }
}

// ---------------------------------------------------------------------------
// K-1b: W1[:,0:512] -> bf16 hi/lo
// ---------------------------------------------------------------------------
__global__ void convB_kernel(const float* __restrict__ W1) {
    int h = blockIdx.x;
    int k = threadIdx.x;
    float x = W1[(size_t)h * NC + k];
    __nv_bfloat16 hi = __float2bfloat16(x);
    g_Bh[h * 512 + k] = hi;
    g_Bl[h * 512 + k] = __float2bfloat16(x - __bfloat162float(hi));
}

// ---------------------------------------------------------------------------
// K0: base[b,h] = b1[h] + sum_c summary[b,c]*W1[h,512+c]
// ---------------------------------------------------------------------------
__global__ void base_kernel(const float* __restrict__ summary,
                            const float* __restrict__ W1,
                            const float* __restrict__ b1) {
    int b = blockIdx.x;
    int h = threadIdx.x;
    __shared__ float ss[512];
    ss[h] = summary[b * 512 + h];
    __syncthreads();
    const float* w = W1 + (size_t)h * NC + 512;
    float acc = b1[h];
#pragma unroll 8
    for (int c = 0; c < 512; c++) acc += ss[c] * w[c];
    g_base[b * NH + h] = acc;
}

// ---------------------------------------------------------------------------
// K1: HMMA GEMM, all 512 h per CTA (4 h-tiles looped), early exit on mask.
// Grid 1024, 256 threads = 8 warps (4 m-quads x 2 n-halves).
// ---------------------------------------------------------------------------
__global__ __launch_bounds__(256, 1) void gemm_kernel(
    const float* __restrict__ W1, const float* __restrict__ W2,
    const float* __restrict__ coverage, const int* __restrict__ tlen) {
    extern __shared__ char smem[];
    const uint32_t sb = smem_u32(smem);
    const int tid = threadIdx.x;
    const int lane = tid & 31;
    const int warp = tid >> 5;
    const int wm = warp & 3;
    const int wn = warp >> 2;

    const int bid = blockIdx.x;
    const int b = bid >> 5;
    const int l0 = (bid & 31) * 128;
    if (l0 >= tlen[b]) return;
    const size_t m0 = (size_t)bid * MT;

    float* s_w2 = (float*)(smem + SM_TAB);           // 128
    float* s_base = (float*)(smem + SM_TAB + 512);   // 128
    float* s_wcov = (float*)(smem + SM_TAB + 1024);  // 128
    float* s_red = (float*)(smem + SM_TAB + 1536);   // 128 x 2
    float* s_lac = (float*)(smem + SM_TAB + 2560);   // 128

    if (tid < 128) s_lac[tid] = 0.0f;

    const uint32_t aBase =
        sb + (uint32_t)((wm * 32 + (lane & 15)) * ROWB + (lane >> 4) * 16);
    const uint32_t bBase =
        sb + 2 * TILEB +
        (uint32_t)((wn * 64 + (lane & 7) + ((lane >> 4) & 1) * 8) * ROWB +
                   ((lane >> 3) & 1) * 16);

    // per-thread cp.async coordinates: 1024 16B chunks per tile, 4 per thread
    const int cr0 = tid >> 3;          // row block base (0..31), +32 per i
    const int cc = tid & 7;            // 16B chunk in row

    for (int ht = 0; ht < 4; ht++) {
        const int h0 = ht * 128;

        float acc[2][8][4];
#pragma unroll
        for (int i = 0; i < 2; i++)
#pragma unroll
            for (int j = 0; j < 8; j++)
#pragma unroll
                for (int c = 0; c < 4; c++) acc[i][j][c] = 0.0f;

        // ---- prologue: stage 0 into buffer 0 ----
        {
#pragma unroll
            for (int i = 0; i < 4; i++) {
                int r = cr0 + i * 32;
                uint32_t d = sb + (uint32_t)(r * ROWB + cc * 16);
                const size_t sa = (m0 + r) * 512 + cc * 8;
                const size_t sbofs = (size_t)(h0 + r) * 512 + cc * 8;
                cpasync16(d, g_Ah + sa);
                cpasync16(d + TILEB, g_Al + sa);
                cpasync16(d + 2 * TILEB, g_Bh + sbofs);
                cpasync16(d + 3 * TILEB, g_Bl + sbofs);
            }
            CP_COMMIT();
            if (tid < 128) {  // tables overlap with TMA-less async loads
                int h = h0 + tid;
                s_w2[tid] = W2[h];
                s_base[tid] = g_base[b * NH + h];
                s_wcov[tid] = W1[(size_t)h * NC + 1024];
            }
            CP_WAIT0();
            __syncthreads();
        }

        // ---- main loop ----
        for (int s = 0; s < NSTAGES; s++) {
            const uint32_t bo = (uint32_t)((s & 1) * BUFB);
            const uint32_t nbo = bo ^ BUFB;

            if (s < NSTAGES - 1) {
                const int k0n = (s + 1) * KC;
#pragma unroll
                for (int i = 0; i < 4; i++) {
                    int r = cr0 + i * 32;
                    uint32_t d = sb + nbo + (uint32_t)(r * ROWB + cc * 16);
                    const size_t sa = (m0 + r) * 512 + k0n + cc * 8;
                    const size_t sbofs = (size_t)(h0 + r) * 512 + k0n + cc * 8;
                    cpasync16(d, g_Ah + sa);
                    cpasync16(d + TILEB, g_Al + sa);
                    cpasync16(d + 2 * TILEB, g_Bh + sbofs);
                    cpasync16(d + 3 * TILEB, g_Bl + sbofs);
                }
                CP_COMMIT();
            }

#pragma unroll
            for (int ks = 0; ks < 4; ks++) {
                uint32_t ah0, ah1, ah2, ah3, ah4, ah5, ah6, ah7;
                uint32_t al0, al1, al2, al3, al4, al5, al6, al7;
                ldsm4(aBase + bo + ks * 32, ah0, ah1, ah2, ah3);
                ldsm4(aBase + bo + ks * 32 + 16 * ROWB, ah4, ah5, ah6, ah7);
                ldsm4(aBase + bo + TILEB + ks * 32, al0, al1, al2, al3);
                ldsm4(aBase + bo + TILEB + ks * 32 + 16 * ROWB, al4, al5, al6,
                      al7);
#pragma unroll
                for (int tp = 0; tp < 4; tp++) {
                    uint32_t bh0, bh1, bh2, bh3, bl0, bl1, bl2, bl3;
                    ldsm4(bBase + bo + ks * 32 + tp * 16 * ROWB, bh0, bh1, bh2,
                          bh3);
                    ldsm4(bBase + bo + TILEB + ks * 32 + tp * 16 * ROWB, bl0,
                          bl1, bl2, bl3);
                    // Ah x Bh
                    mma16816(acc[0][2 * tp], ah0, ah1, ah2, ah3, bh0, bh1);
                    mma16816(acc[0][2 * tp + 1], ah0, ah1, ah2, ah3, bh2, bh3);
                    mma16816(acc[1][2 * tp], ah4, ah5, ah6, ah7, bh0, bh1);
                    mma16816(acc[1][2 * tp + 1], ah4, ah5, ah6, ah7, bh2, bh3);
                    // Ah x Bl
                    mma16816(acc[0][2 * tp], ah0, ah1, ah2, ah3, bl0, bl1);
                    mma16816(acc[0][2 * tp + 1], ah0, ah1, ah2, ah3, bl2, bl3);
                    mma16816(acc[1][2 * tp], ah4, ah5, ah6, ah7, bl0, bl1);
                    mma16816(acc[1][2 * tp + 1], ah4, ah5, ah6, ah7, bl2, bl3);
                    // Al x Bh
                    mma16816(acc[0][2 * tp], al0, al1, al2, al3, bh0, bh1);
                    mma16816(acc[0][2 * tp + 1], al0, al1, al2, al3, bh2, bh3);
                    mma16816(acc[1][2 * tp], al4, al5, al6, al7, bh0, bh1);
                    mma16816(acc[1][2 * tp + 1], al4, al5, al6, al7, bh2, bh3);
                }
            }

            if (s < NSTAGES - 1) CP_WAIT0();
            __syncthreads();
        }

        // ---- epilogue for this h-tile ----
#pragma unroll
        for (int tm = 0; tm < 2; tm++) {
#pragma unroll
            for (int rh = 0; rh < 2; rh++) {
                int m_local = wm * 32 + tm * 16 + rh * 8 + (lane >> 2);
                float cov = coverage[m0 + m_local];
                float rs = 0.0f;
#pragma unroll
                for (int tn = 0; tn < 8; tn++) {
                    int h = wn * 64 + tn * 8 + (lane & 3) * 2;
                    float p0 =
                        acc[tm][tn][rh * 2 + 0] + s_base[h] + cov * s_wcov[h];
                    float p1 = acc[tm][tn][rh * 2 + 1] + s_base[h + 1] +
                               cov * s_wcov[h + 1];
                    rs += fast_tanh(p0) * s_w2[h] + fast_tanh(p1) * s_w2[h + 1];
                }
                rs += __shfl_xor_sync(0xffffffffu, rs, 1);
                rs += __shfl_xor_sync(0xffffffffu, rs, 2);
                if ((lane & 3) == 0) s_red[m_local * 2 + wn] = rs;
            }
        }
        __syncthreads();
        if (tid < 128) s_lac[tid] += s_red[tid * 2] + s_red[tid * 2 + 1];
        __syncthreads();
    }

    if (tid < 128) g_logits[m0 + tid] = s_lac[tid];
}

// ---------------------------------------------------------------------------
// K3: per-batch masked softmax
// ---------------------------------------------------------------------------
__global__ __launch_bounds__(256) void softmax_kernel(const int* __restrict__ tlen,
                                                      float* __restrict__ att_out) {
    int b = blockIdx.x;
    int tid = threadIdx.x;
    __shared__ float sl[NL];
    __shared__ float rbuf[256];
    int len = tlen[b];

    for (int l = tid; l < len; l += 256) sl[l] = g_logits[b * NL + l];
    __syncthreads();

    float mx = -INFINITY;
    for (int l = tid; l < len; l += 256) mx = fmaxf(mx, sl[l]);
    rbuf[tid] = mx;
    __syncthreads();
    for (int s = 128; s > 0; s >>= 1) {
        if (tid < s) rbuf[tid] = fmaxf(rbuf[tid], rbuf[tid + s]);
        __syncthreads();
    }
    mx = rbuf[0];
    __syncthreads();

    float sum = 0.0f;
    for (int l = tid; l < len; l += 256) {
        float e = fast_exp(sl[l] - mx);
        sl[l] = e;
        sum += e;
    }
    rbuf[tid] = sum;
    __syncthreads();
    for (int s = 128; s > 0; s >>= 1) {
        if (tid < s) rbuf[tid] = rbuf[tid] + rbuf[tid + s];
        __syncthreads();
    }
    float inv = 1.0f / rbuf[0];

    for (int l = tid; l < NL; l += 256)
        att_out[b * NL + l] = (l < len) ? sl[l] * inv : 0.0f;
}

// ---------------------------------------------------------------------------
// K4/K5: context partials + reduce
// ---------------------------------------------------------------------------
__global__ __launch_bounds__(256) void ctx_part_kernel(
    const float* __restrict__ ts, const float* __restrict__ att,
    const int* __restrict__ tlen) {
    int b = blockIdx.x;
    int c = blockIdx.y;
    int tid = threadIdx.x;
    float* out = g_ctx_part + ((size_t)c * NB + b) * 512;

    if (c * 128 >= tlen[b]) {
        out[tid] = 0.0f;
        out[tid + 256] = 0.0f;
        return;
    }

    __shared__ float sa[128];
    if (tid < 128) sa[tid] = att[b * NL + c * 128 + tid];
    __syncthreads();

    const float* base = ts + ((size_t)b * NL + c * 128) * 512;
    float a0 = 0.f, a1 = 0.f;
#pragma unroll 4
    for (int l = 0; l < 128; l++) {
        float wv = sa[l];
        a0 += wv * base[(size_t)l * 512 + tid];
        a1 += wv * base[(size_t)l * 512 + 256 + tid];
    }
    out[tid] = a0;
    out[tid + 256] = a1;
}

__global__ __launch_bounds__(512) void ctx_reduce_kernel(float* __restrict__ ctx) {
    int b = blockIdx.x;
    int f = threadIdx.x;
    float s = 0.0f;
#pragma unroll
    for (int c = 0; c < 32; c++) s += g_ctx_part[((size_t)c * NB + b) * 512 + f];
    ctx[b * 512 + f] = s;
}

// ---------------------------------------------------------------------------
// Launch
// ---------------------------------------------------------------------------
extern "C" void kernel_launch(void* const* d_in, const int* in_sizes, int n_in,
                              void* d_out, int out_size) {
    const float* ts  = (const float*)d_in[0];
    const float* ss  = (const float*)d_in[1];
    const float* cov = (const float*)d_in[2];
    const float* W1  = (const float*)d_in[3];
    const float* b1  = (const float*)d_in[4];
    const float* W2  = (const float*)d_in[5];
    const int*   tl  = (const int*)d_in[7];
    float* out = (float*)d_out;
    float* ctx_out = out;             // [32,512]
    float* att_out = out + NB * 512;  // [32,4096]

    cudaFuncSetAttribute(gemm_kernel,
                         cudaFuncAttributeMaxDynamicSharedMemorySize, SMEM_TOTAL);

    convA_kernel<<<1024, 256>>>(ts, tl);
    convB_kernel<<<NH, 512>>>(W1);
    base_kernel<<<NB, 512>>>(ss, W1, b1);
    gemm_kernel<<<1024, 256, SMEM_TOTAL>>>(W1, W2, cov, tl);
    softmax_kernel<<<NB, 256>>>(tl, att_out);
    ctx_part_kernel<<<dim3(NB, 32), 256>>>(ts, att_out, tl);
    ctx_reduce_kernel<<<NB, 512>>>(ctx_out);
}